// round 14
// baseline (speedup 1.0000x reference)
#include <cuda_runtime.h>
#include <math.h>

// ---------------- problem constants ----------------
#define B       2
#define C       128
#define H0      384
#define W0      512
#define H1      192
#define W1      256
#define N0      (H0*W0)     // 196608
#define N1      (H1*W1)     // 49152
#define K_KP    512
#define K_MATCH 128
#define CAP     32768
#define MKEEP   4096
#define THRESH  0.7f
#define INVTEMP 512.0f
#define EXPCUT  (-0.1f)     // exp(512*-0.1)=6e-23: negligible vs retained terms

// ---------------- device scratch ----------------
__device__ float g_cand_score[4][CAP];
__device__ int   g_cand_idx[4][CAP];
__device__ int   g_cand_count[4];          // zeroed by gather for next replay
__device__ float g_kp_score[4][K_KP];
__device__ int   g_kp_idx[4][K_KP];
__device__ float g_desc[4][C][K_KP];       // gathered desc * score
__device__ float g_loc[4][2][K_KP];        // [row][{r,c}][k]
__device__ float g_M[C][C];                // Wq^T * Wk
__device__ float g_part[B][2][K_KP][5];    // per-m-half online state {m1,m2,sw,y0,y1}

// ---------------- cp.async helpers ----------------
__device__ __forceinline__ void cp16(void* s, const void* g) {
    unsigned sa = (unsigned)__cvta_generic_to_shared(s);
    asm volatile("cp.async.cg.shared.global [%0], [%1], 16;" :: "r"(sa), "l"(g) : "memory");
}
#define CP_COMMIT()  asm volatile("cp.async.commit_group;" ::: "memory")
#define CP_WAIT1()   asm volatile("cp.async.wait_group 1;" ::: "memory")
#define CP_WAIT0()   asm volatile("cp.async.wait_group 0;" ::: "memory")

// ---------------- kernel 1: score + NMS (+ M = Wq^T Wk on z==8) ----------------
__global__ void score_all_kernel(const float* __restrict__ rep10, const float* __restrict__ rel10,
                                 const float* __restrict__ rep11, const float* __restrict__ rel11,
                                 const float* __restrict__ rep20, const float* __restrict__ rel20,
                                 const float* __restrict__ rep21, const float* __restrict__ rel21,
                                 const float* __restrict__ Wq,  const float* __restrict__ Wk) {
    int z = blockIdx.z;
    if (z == 8) {
        int mb = blockIdx.y * gridDim.x + blockIdx.x;
        if (mb >= 16) return;
        int c1_0 = (mb >> 2) * 32, c2_0 = (mb & 3) * 32;
        __shared__ float wqs[32][33];
        __shared__ float wks[32][33];
        int tid = threadIdx.x;               // 256
        int c1l = tid >> 3;
        int c2q = (tid & 7) * 4;
        float acc[4] = {0.f, 0.f, 0.f, 0.f};
        for (int r0 = 0; r0 < C; r0 += 32) {
            for (int i = tid; i < 32 * 32; i += 256) {
                int rr = i >> 5, cc = i & 31;
                wqs[rr][cc] = Wq[(r0 + rr) * C + c1_0 + cc];
                wks[rr][cc] = Wk[(r0 + rr) * C + c2_0 + cc];
            }
            __syncthreads();
            #pragma unroll
            for (int rr = 0; rr < 32; ++rr) {
                float wq = wqs[rr][c1l];
                #pragma unroll
                for (int j = 0; j < 4; ++j) acc[j] += wq * wks[rr][c2q + j];
            }
            __syncthreads();
        }
        #pragma unroll
        for (int j = 0; j < 4; ++j) g_M[c1_0 + c1l][c2_0 + c2q + j] = acc[j];
        return;
    }

    int img  = z >> 2;
    int scal = (z >> 1) & 1;
    int b    = z & 1;
    const float *rep, *rel;
    int H, W, nOff;
    if (scal == 0) { rep = img ? rep20 : rep10; rel = img ? rel20 : rel10; H = H0; W = W0; nOff = 0;  }
    else           { rep = img ? rep21 : rep11; rel = img ? rel21 : rel11; H = H1; W = W1; nOff = N0; }
    int gx0 = blockIdx.x * 128, gy0 = blockIdx.y * 8;
    if (gx0 >= W || gy0 >= H) return;
    int row = img * 2 + b;

    __shared__ float s[10][132];
    __shared__ float c_sc[1024];
    __shared__ int   c_ix[1024];
    __shared__ int   c_cnt, c_base;

    int tid = threadIdx.x;
    const float* repb = rep + b * (H * W);
    const float* relb = rel + b * (H * W);

    if (tid == 0) c_cnt = 0;
    for (int i = tid; i < 10 * 132; i += 256) {
        int ly = i / 132, lx = i - ly * 132;
        if (lx < 130) {
            int gy = gy0 + ly - 1, gx = gx0 + lx - 1;
            float v = -INFINITY;
            if (gy >= 0 && gy < H && gx >= 0 && gx < W) v = repb[gy * W + gx];
            s[ly][lx] = v;
        }
    }
    __syncthreads();

    int tx = tid & 31, ty = tid >> 5;     // 32 x 8, 4 px/thread
    int gy = gy0 + ty;
    int cx = tx * 4;
    float4 e4 = *(const float4*)&relb[gy * W + gx0 + cx];
    float ev[4] = {e4.x, e4.y, e4.z, e4.w};
    #pragma unroll
    for (int px = 0; px < 4; ++px) {
        float v = s[ty + 1][cx + px + 1];
        float mean = sqrtf(v * ev[px]);
        if (mean >= THRESH) {
            float nb = fmaxf(fmaxf(s[ty][cx + px],     s[ty][cx + px + 1]),
                             fmaxf(s[ty][cx + px + 2], s[ty + 1][cx + px]));
            nb = fmaxf(nb, fmaxf(fmaxf(s[ty + 1][cx + px + 2], s[ty + 2][cx + px]),
                                 fmaxf(s[ty + 2][cx + px + 1], s[ty + 2][cx + px + 2])));
            if (!(nb > v)) {
                int p = atomicAdd(&c_cnt, 1);
                c_sc[p] = mean;
                c_ix[p] = nOff + gy * W + gx0 + cx + px;
            }
        }
    }
    __syncthreads();
    int cnt = c_cnt;
    if (cnt == 0) return;
    if (tid == 0) c_base = atomicAdd(&g_cand_count[row], cnt);
    __syncthreads();
    int base = c_base;
    for (int i = tid; i < cnt; i += 256) {
        int pos = base + i;
        if (pos < CAP) {
            g_cand_score[row][pos] = c_sc[i];
            g_cand_idx[row][pos]   = c_ix[i];
        }
    }
}

// ---------------- kernel 2: per-row top-512 (bin-bucketed exact rank) ----------------
__global__ void topk_kernel() {
    __shared__ int   hist[1024];
    __shared__ int   sfxs[1025];
    __shared__ int   fill[1024];
    __shared__ int   wtot[32];
    __shared__ int   wtail[32];
    __shared__ float ks_[MKEEP];
    __shared__ int   ki_[MKEEP];
    __shared__ int   s_thr;
    int row = blockIdx.x;
    int tid = threadIdx.x;              // 1024 threads
    int lane = tid & 31, wid = tid >> 5;
    int count = min(g_cand_count[row], CAP);

    hist[tid] = 0;
    fill[tid] = 0;
    if (tid == 0) { s_thr = 0; sfxs[1024] = 0; }
    __syncthreads();

    const float SCL = 1024.0f / 0.3f;
    for (int i = tid; i < count; i += 1024) {
        float sc = g_cand_score[row][i];
        int bb = max(0, min(1023, (int)((sc - THRESH) * SCL)));
        atomicAdd(&hist[bb], 1);
    }
    __syncthreads();

    // suffix count via warp shuffles: sfxs[tid] = sum(hist[tid..1023])
    int h = hist[tid];
    int sfx = h;
    #pragma unroll
    for (int off = 1; off < 32; off <<= 1) {
        int v = __shfl_down_sync(0xffffffffu, sfx, off);
        if (lane < 32 - off) sfx += v;
    }
    int tot = __shfl_sync(0xffffffffu, sfx, 0);   // warp total
    if (lane == 0) wtot[wid] = tot;
    __syncthreads();
    if (tid < 32) {
        int t = wtot[tid];
        int inc = t;
        #pragma unroll
        for (int off = 1; off < 32; off <<= 1) {
            int v = __shfl_down_sync(0xffffffffu, inc, off);
            if (tid < 32 - off) inc += v;
        }
        wtail[tid] = inc - t;     // sum of totals of LATER warps
    }
    __syncthreads();
    {
        int cge = sfx + wtail[wid];
        sfxs[tid] = cge;
        int cge_next = cge - h;
        if (cge >= K_KP && cge_next < K_KP) s_thr = tid;   // unique writer
    }
    __syncthreads();

    int thr = s_thr;
    int kept = min(sfxs[thr], MKEEP);

    // scatter survivors into bin-ordered segments: bin b -> [sfxs[b+1], sfxs[b])
    for (int i = tid; i < count; i += 1024) {
        float sc = g_cand_score[row][i];
        int bb = max(0, min(1023, (int)((sc - THRESH) * SCL)));
        if (bb >= thr) {
            int slot = sfxs[bb + 1] + atomicAdd(&fill[bb], 1);
            if (slot < MKEEP) { ks_[slot] = sc; ki_[slot] = g_cand_idx[row][i]; }
        }
    }
    __syncthreads();

    // exact rank = segment base + within-bin rank (bins strictly ordered by score)
    for (int s2 = tid; s2 < kept; s2 += 1024) {
        float si = ks_[s2]; int ii = ki_[s2];
        int bn = max(0, min(1023, (int)((si - THRESH) * SCL)));
        int lo = sfxs[bn + 1], hi = min(sfxs[bn], kept);
        int rank = lo;
        for (int j = lo; j < hi; ++j) {
            float sj = ks_[j];
            rank += (sj > si) || (sj == si && ki_[j] < ii);
        }
        if (rank < K_KP) { g_kp_score[row][rank] = si; g_kp_idx[row][rank] = ii; }
    }
    __syncthreads();
    if (kept < K_KP) {   // degenerate padding; won't trigger on this data
        for (int r2 = kept + tid; r2 < K_KP; r2 += 1024) {
            g_kp_score[row][r2] = -1.0f;
            g_kp_idx[row][r2]   = r2 - kept;
        }
    }
}

// ---------------- kernel 3: scattered gather (all rows) ----------------
__global__ void gather_kernel(const float* __restrict__ d1s0, const float* __restrict__ d1s1,
                              const float* __restrict__ d2s0, const float* __restrict__ d2s1) {
    int bid = blockIdx.x;
    if (bid == 0 && threadIdx.x < 4) g_cand_count[threadIdx.x] = 0;  // reset for next replay
    int row = bid >> 8;                               // 256 blocks per row
    int t   = (bid & 255) * 256 + threadIdx.x;        // over C*K_KP, kpos fastest
    int ch  = t >> 9;
    int kp  = t & (K_KP - 1);
    int img = row >> 1, b = row & 1;

    int   idx = g_kp_idx[row][kp];
    float sc  = g_kp_score[row][kp];

    const float* dsc; int HW, p;
    if (idx < N0) { dsc = img ? d2s0 : d1s0; HW = N0; p = idx; }
    else          { dsc = img ? d2s1 : d1s1; HW = N1; p = idx - N0; }
    g_desc[row][ch][kp] = __ldg(&dsc[(b * C + ch) * HW + p]) * sc;

    if (ch < 2) {
        int W, pp; float scale;
        if (idx < N0) { W = W0; pp = idx;      scale = 1.0f; }
        else          { W = W1; pp = idx - N0; scale = 2.0f; }
        int r = pp / W, c2 = pp - r * W;
        g_loc[row][ch][kp] = (ch == 0 ? (float)r : (float)c2) * scale;
    }
}

// ---------------- kernel 4: relmatch over one m-HALF ----------------
// grid (128, B): blockIdx.x = (ntile<<1)|mhalf. 256 threads.
// Block = 8 q-rows x 256 m; thread tile 2 rows x 4 m; cp.async double buffer.
// Emits per-row online state {m1,m2,sw,y0,y1} to g_part[b][mhalf][n].
#define MH 256   // m per block
struct Ph1 { float qs[C][8]; float Ms[32][C]; };
union PhU { Ph1 p1; float kss[2][32][MH]; };   // 64 KB

__global__ __launch_bounds__(256)
void relmatch_kernel(const float* __restrict__ Wv) {
    __shared__ float qmsT[C][10];    // [channel][row], padded
    __shared__ float locs[2][MH];
    __shared__ float pst[8][2][5];
    __shared__ float s_wv[4];
    __shared__ PhU u;
    int b     = blockIdx.y;
    int n0    = (blockIdx.x >> 1) * 8;
    int mhalf = blockIdx.x & 1;
    int mg0   = mhalf * MH;          // global m base
    int tid = threadIdx.x;           // 256
    int w   = tid >> 5, lane = tid & 31;
    int krow = 2 + b;

    // ---- prefetch locs via cp.async (group #0) ----
    if (tid < 128) {
        int ch = tid >> 6, j = (tid & 63) * 4;
        cp16(&locs[ch][j], &g_loc[krow][ch][mg0 + j]);
    }
    CP_COMMIT();

    // ---- stage q rows: qs[c][r] ----
    {
        int c = tid >> 1, part = tid & 1;
        float4 v = *(const float4*)&g_desc[b][c][n0 + part * 4];
        *(float4*)&u.p1.qs[c][part * 4] = v;
    }
    if (tid < 4) s_wv[tid] = Wv[tid];
    __syncthreads();

    // ---- qm[r][c'] = sum_c q[c][r] * M[c][c'];  warp w owns row w ----
    for (int c0 = 0; c0 < C; c0 += 32) {
        #pragma unroll
        for (int k = 0; k < 4; ++k) {
            int i = tid + 256 * k;          // float4 index into 32x128 tile
            int cc = i >> 5, c4 = i & 31;
            *(float4*)&u.p1.Ms[cc][c4 * 4] = *(const float4*)&g_M[c0 + cc][c4 * 4];
        }
        __syncthreads();
        float qacc[4] = {0.f, 0.f, 0.f, 0.f};
        #pragma unroll
        for (int cc = 0; cc < 32; ++cc) {
            float qc = u.p1.qs[c0 + cc][w];
            float4 mv = *(const float4*)&u.p1.Ms[cc][lane * 4];
            qacc[0] += qc * mv.x; qacc[1] += qc * mv.y;
            qacc[2] += qc * mv.z; qacc[3] += qc * mv.w;
        }
        if (c0 == 0) {
            #pragma unroll
            for (int j = 0; j < 4; ++j) qmsT[lane * 4 + j][w] = qacc[j];
        } else {
            #pragma unroll
            for (int j = 0; j < 4; ++j) qmsT[lane * 4 + j][w] += qacc[j];
        }
        __syncthreads();
    }
    // (accumulated in ascending c0 order: deterministic running sum)

    float wv00 = s_wv[0], wv01 = s_wv[1], wv10 = s_wv[2], wv11 = s_wv[3];

    int rp = tid >> 6;               // 0..3 row-pair
    int mq = tid & 63;               // 0..63 m-quad within block
    int r0 = 2 * rp, r1 = r0 + 1;

    // ---- pipelined k staging ----
    #define STAGE_FILL(buf, c0) do { \
        _Pragma("unroll") \
        for (int k = 0; k < 8; ++k) { \
            int i = tid + 256 * k; \
            int cc = i >> 6, m4 = i & 63; \
            cp16(&u.kss[buf][cc][m4 * 4], &g_desc[krow][(c0) + cc][mg0 + m4 * 4]); \
        } \
    } while (0)

    STAGE_FILL(0, 0);
    CP_COMMIT();

    float s0[4] = {0.f, 0.f, 0.f, 0.f}, s1[4] = {0.f, 0.f, 0.f, 0.f};
    #pragma unroll
    for (int st = 0; st < 4; ++st) {
        if (st < 3) {
            STAGE_FILL((st + 1) & 1, 32 * (st + 1));
            CP_COMMIT();
            CP_WAIT1();
        } else {
            CP_WAIT0();
        }
        __syncthreads();
        int c0 = 32 * st;
        const float* kbase = &u.kss[st & 1][0][mq * 4];
        #pragma unroll
        for (int cc = 0; cc < 32; ++cc) {
            float2 q2 = *(const float2*)&qmsT[c0 + cc][r0];
            float4 kv = *(const float4*)(kbase + cc * MH);
            s0[0] += q2.x * kv.x; s0[1] += q2.x * kv.y;
            s0[2] += q2.x * kv.z; s0[3] += q2.x * kv.w;
            s1[0] += q2.y * kv.x; s1[1] += q2.y * kv.y;
            s1[2] += q2.y * kv.z; s1[3] += q2.y * kv.w;
        }
        __syncthreads();
    }
    #undef STAGE_FILL

    // ---- online top2 + softmax updates (exp-skip below EXPCUT) ----
    float m1a = -2.f, m2a = -2.f, swa = 0.f, ya0 = 0.f, ya1 = 0.f;
    float m1b = -2.f, m2b = -2.f, swb = 0.f, yb0 = 0.f, yb1 = 0.f;
    #pragma unroll
    for (int j = 0; j < 4; ++j) {
        int m = mq * 4 + j;
        float l0 = locs[0][m], l1 = locs[1][m];
        float vv0 = wv00 * l0 + wv01 * l1;
        float vv1 = wv10 * l0 + wv11 * l1;
        float v = s0[j];
        if (v > m1a) {
            float d = m1a - v;
            float f = (d < EXPCUT) ? 0.f : expf(INVTEMP * d);
            swa = swa * f + 1.f; ya0 = ya0 * f + vv0; ya1 = ya1 * f + vv1;
            m2a = m1a; m1a = v;
        } else {
            if (v > m2a) m2a = v;
            float d = v - m1a;
            if (d >= EXPCUT) {
                float e = expf(INVTEMP * d);
                swa += e; ya0 += e * vv0; ya1 += e * vv1;
            }
        }
        v = s1[j];
        if (v > m1b) {
            float d = m1b - v;
            float f = (d < EXPCUT) ? 0.f : expf(INVTEMP * d);
            swb = swb * f + 1.f; yb0 = yb0 * f + vv0; yb1 = yb1 * f + vv1;
            m2b = m1b; m1b = v;
        } else {
            if (v > m2b) m2b = v;
            float d = v - m1b;
            if (d >= EXPCUT) {
                float e = expf(INVTEMP * d);
                swb += e; yb0 += e * vv0; yb1 += e * vv1;
            }
        }
    }

    // ---- warp merge (warp covers m-chunk of 128) ----
    #pragma unroll
    for (int off = 16; off; off >>= 1) {
        float o1, o2, os, o0, oy;
        o1 = __shfl_down_sync(0xffffffffu, m1a, off);
        o2 = __shfl_down_sync(0xffffffffu, m2a, off);
        os = __shfl_down_sync(0xffffffffu, swa, off);
        o0 = __shfl_down_sync(0xffffffffu, ya0, off);
        oy = __shfl_down_sync(0xffffffffu, ya1, off);
        if (o1 > m1a) {
            float t;
            t = m1a; m1a = o1; o1 = t;
            t = m2a; m2a = o2; o2 = t;
            t = swa; swa = os; os = t;
            t = ya0; ya0 = o0; o0 = t;
            t = ya1; ya1 = oy; oy = t;
        }
        m2a = fmaxf(m2a, o1);
        float d = o1 - m1a;
        float f = (d < EXPCUT) ? 0.f : expf(INVTEMP * d);
        swa += f * os; ya0 += f * o0; ya1 += f * oy;

        o1 = __shfl_down_sync(0xffffffffu, m1b, off);
        o2 = __shfl_down_sync(0xffffffffu, m2b, off);
        os = __shfl_down_sync(0xffffffffu, swb, off);
        o0 = __shfl_down_sync(0xffffffffu, yb0, off);
        oy = __shfl_down_sync(0xffffffffu, yb1, off);
        if (o1 > m1b) {
            float t;
            t = m1b; m1b = o1; o1 = t;
            t = m2b; m2b = o2; o2 = t;
            t = swb; swb = os; os = t;
            t = yb0; yb0 = o0; o0 = t;
            t = yb1; yb1 = oy; oy = t;
        }
        m2b = fmaxf(m2b, o1);
        d = o1 - m1b;
        f = (d < EXPCUT) ? 0.f : expf(INVTEMP * d);
        swb += f * os; yb0 += f * o0; yb1 += f * oy;
    }
    if (lane == 0) {
        int frag = w & 1;                 // m-chunk order: 0, 128
        float* pa = pst[r0][frag];
        pa[0] = m1a; pa[1] = m2a; pa[2] = swa; pa[3] = ya0; pa[4] = ya1;
        float* pb = pst[r1][frag];
        pb[0] = m1b; pb[1] = m2b; pb[2] = swb; pb[3] = yb0; pb[4] = yb1;
    }
    __syncthreads();

    // ---- in-block merge of 2 fragments; emit partial state ----
    if (tid < 8) {
        const float* h0 = pst[tid][0];
        const float* h1 = pst[tid][1];
        float m1 = h0[0], m2 = h0[1], sw = h0[2], y0 = h0[3], y1 = h0[4];
        float o1 = h1[0], o2 = h1[1], os = h1[2], o0 = h1[3], oy = h1[4];
        if (o1 > m1) {
            float t;
            t = m1; m1 = o1; o1 = t;
            t = m2; m2 = o2; o2 = t;
            t = sw; sw = os; os = t;
            t = y0; y0 = o0; o0 = t;
            t = y1; y1 = oy; oy = t;
        }
        m2 = fmaxf(m2, o1);
        float d = o1 - m1;
        float f = (d < EXPCUT) ? 0.f : expf(INVTEMP * d);
        sw += f * os; y0 += f * o0; y1 += f * oy;

        int n = n0 + tid;
        float* pg = g_part[b][mhalf][n];
        pg[0] = m1; pg[1] = m2; pg[2] = sw; pg[3] = y0; pg[4] = y1;
    }
}

// ---------------- kernel 5: merge m-halves + acos ratio + final top-128 ----------------
__global__ void merge_final_kernel(float* __restrict__ out) {
    __shared__ float rs[K_KP];
    __shared__ float ys0[K_KP];
    __shared__ float ys1[K_KP];
    int b = blockIdx.x, tid = threadIdx.x;  // 512
    {
        const float* h0 = g_part[b][0][tid];
        const float* h1 = g_part[b][1][tid];
        float m1 = h0[0], m2 = h0[1], sw = h0[2], y0 = h0[3], y1 = h0[4];
        float o1 = h1[0], o2 = h1[1], os = h1[2], o0 = h1[3], oy = h1[4];
        if (o1 > m1) {
            float t;
            t = m1; m1 = o1; o1 = t;
            t = m2; m2 = o2; o2 = t;
            t = sw; sw = os; os = t;
            t = y0; y0 = o0; o0 = t;
            t = y1; y1 = oy; oy = t;
        }
        m2 = fmaxf(m2, o1);
        float d = o1 - m1;
        float f = (d < EXPCUT) ? 0.f : expf(INVTEMP * d);
        sw += f * os; y0 += f * o0; y1 += f * oy;

        float ac1 = acosf(fminf(fmaxf(m1, -1.0f), 1.0f));
        float ac2 = acosf(fminf(fmaxf(m2, -1.0f), 1.0f));
        rs[tid]  = ac1 / ac2;
        ys0[tid] = y0 / sw;
        ys1[tid] = y1 / sw;
    }
    __syncthreads();
    float ri = rs[tid];
    int rank = 0;
    for (int j = 0; j < K_KP; ++j) {
        float rj = rs[j];
        rank += (rj < ri) || (rj == ri && j < tid);
    }
    if (rank < K_MATCH) {
        out[(b * 4 + 0) * K_MATCH + rank] = g_loc[b][0][tid];
        out[(b * 4 + 1) * K_MATCH + rank] = g_loc[b][1][tid];
        out[(b * 4 + 2) * K_MATCH + rank] = ys0[tid];
        out[(b * 4 + 3) * K_MATCH + rank] = ys1[tid];
    }
}

// ---------------- launch ----------------
extern "C" void kernel_launch(void* const* d_in, const int* in_sizes, int n_in,
                              void* d_out, int out_size) {
    const float* rep1_s0 = (const float*)d_in[0];
    const float* rel1_s0 = (const float*)d_in[1];
    const float* desc1_s0 = (const float*)d_in[2];
    const float* rep1_s1 = (const float*)d_in[3];
    const float* rel1_s1 = (const float*)d_in[4];
    const float* desc1_s1 = (const float*)d_in[5];
    const float* rep2_s0 = (const float*)d_in[6];
    const float* rel2_s0 = (const float*)d_in[7];
    const float* desc2_s0 = (const float*)d_in[8];
    const float* rep2_s1 = (const float*)d_in[9];
    const float* rel2_s1 = (const float*)d_in[10];
    const float* rep2_s1b = rep2_s1; (void)rep2_s1b;
    const float* Wq = (const float*)d_in[12];
    const float* Wk = (const float*)d_in[13];
    const float* Wv = (const float*)d_in[14];
    const float* desc2_s1 = (const float*)d_in[11];
    float* out = (float*)d_out;

    score_all_kernel<<<dim3(W0 / 128, H0 / 8, 9), 256>>>(
        rep1_s0, rel1_s0, rep1_s1, rel1_s1, rep2_s0, rel2_s0, rep2_s1, rel2_s1, Wq, Wk);

    topk_kernel<<<4, 1024>>>();

    gather_kernel<<<1024, 256>>>(desc1_s0, desc1_s1, desc2_s0, desc2_s1);

    relmatch_kernel<<<dim3(128, B), 256>>>(Wv);

    merge_final_kernel<<<B, 512>>>(out);
}

// round 15
// speedup vs baseline: 1.1237x; 1.1237x over previous
#include <cuda_runtime.h>
#include <math.h>

// ---------------- problem constants ----------------
#define B       2
#define C       128
#define H0      384
#define W0      512
#define H1      192
#define W1      256
#define N0      (H0*W0)     // 196608
#define N1      (H1*W1)     // 49152
#define K_KP    512
#define K_MATCH 128
#define CAP     32768
#define MKEEP   4096
#define THRESH  0.7f
#define INVTEMP 512.0f

// ---------------- device scratch ----------------
__device__ float g_cand_score[4][CAP];
__device__ int   g_cand_idx[4][CAP];
__device__ int   g_cand_count[4];          // zeroed by gather for next replay
__device__ float g_kp_score[4][K_KP];
__device__ int   g_kp_idx[4][K_KP];
__device__ float g_desc[4][C][K_KP];       // gathered desc * score
__device__ float g_loc[4][2][K_KP];        // [row][{r,c}][k]
__device__ float g_M[C][C];                // Wq^T * Wk
__device__ float g_ratio[B][K_KP];
__device__ float g_y[B][2][K_KP];

// ---------------- cp.async helpers ----------------
__device__ __forceinline__ void cp16(void* s, const void* g) {
    unsigned sa = (unsigned)__cvta_generic_to_shared(s);
    asm volatile("cp.async.cg.shared.global [%0], [%1], 16;" :: "r"(sa), "l"(g) : "memory");
}
#define CP_COMMIT()  asm volatile("cp.async.commit_group;" ::: "memory")
#define CP_WAIT1()   asm volatile("cp.async.wait_group 1;" ::: "memory")
#define CP_WAIT0()   asm volatile("cp.async.wait_group 0;" ::: "memory")

// ---------------- kernel 1: score + NMS (+ M = Wq^T Wk on z==8) ----------------
__global__ void score_all_kernel(const float* __restrict__ rep10, const float* __restrict__ rel10,
                                 const float* __restrict__ rep11, const float* __restrict__ rel11,
                                 const float* __restrict__ rep20, const float* __restrict__ rel20,
                                 const float* __restrict__ rep21, const float* __restrict__ rel21,
                                 const float* __restrict__ Wq,  const float* __restrict__ Wk) {
    int z = blockIdx.z;
    if (z == 8) {
        int mb = blockIdx.y * gridDim.x + blockIdx.x;
        if (mb >= 16) return;
        int c1_0 = (mb >> 2) * 32, c2_0 = (mb & 3) * 32;
        __shared__ float wqs[32][33];
        __shared__ float wks[32][33];
        int tid = threadIdx.x;               // 256
        int c1l = tid >> 3;
        int c2q = (tid & 7) * 4;
        float acc[4] = {0.f, 0.f, 0.f, 0.f};
        for (int r0 = 0; r0 < C; r0 += 32) {
            for (int i = tid; i < 32 * 32; i += 256) {
                int rr = i >> 5, cc = i & 31;
                wqs[rr][cc] = Wq[(r0 + rr) * C + c1_0 + cc];
                wks[rr][cc] = Wk[(r0 + rr) * C + c2_0 + cc];
            }
            __syncthreads();
            #pragma unroll
            for (int rr = 0; rr < 32; ++rr) {
                float wq = wqs[rr][c1l];
                #pragma unroll
                for (int j = 0; j < 4; ++j) acc[j] += wq * wks[rr][c2q + j];
            }
            __syncthreads();
        }
        #pragma unroll
        for (int j = 0; j < 4; ++j) g_M[c1_0 + c1l][c2_0 + c2q + j] = acc[j];
        return;
    }

    int img  = z >> 2;
    int scal = (z >> 1) & 1;
    int b    = z & 1;
    const float *rep, *rel;
    int H, W, nOff;
    if (scal == 0) { rep = img ? rep20 : rep10; rel = img ? rel20 : rel10; H = H0; W = W0; nOff = 0;  }
    else           { rep = img ? rep21 : rep11; rel = img ? rel21 : rel11; H = H1; W = W1; nOff = N0; }
    int gx0 = blockIdx.x * 128, gy0 = blockIdx.y * 8;
    if (gx0 >= W || gy0 >= H) return;
    int row = img * 2 + b;

    __shared__ float s[10][132];
    __shared__ float c_sc[1024];
    __shared__ int   c_ix[1024];
    __shared__ int   c_cnt, c_base;

    int tid = threadIdx.x;
    const float* repb = rep + b * (H * W);
    const float* relb = rel + b * (H * W);

    if (tid == 0) c_cnt = 0;
    for (int i = tid; i < 10 * 132; i += 256) {
        int ly = i / 132, lx = i - ly * 132;
        if (lx < 130) {
            int gy = gy0 + ly - 1, gx = gx0 + lx - 1;
            float v = -INFINITY;
            if (gy >= 0 && gy < H && gx >= 0 && gx < W) v = repb[gy * W + gx];
            s[ly][lx] = v;
        }
    }
    __syncthreads();

    int tx = tid & 31, ty = tid >> 5;     // 32 x 8, 4 px/thread
    int gy = gy0 + ty;
    int cx = tx * 4;
    float4 e4 = *(const float4*)&relb[gy * W + gx0 + cx];
    float ev[4] = {e4.x, e4.y, e4.z, e4.w};
    #pragma unroll
    for (int px = 0; px < 4; ++px) {
        float v = s[ty + 1][cx + px + 1];
        float mean = sqrtf(v * ev[px]);
        if (mean >= THRESH) {
            float nb = fmaxf(fmaxf(s[ty][cx + px],     s[ty][cx + px + 1]),
                             fmaxf(s[ty][cx + px + 2], s[ty + 1][cx + px]));
            nb = fmaxf(nb, fmaxf(fmaxf(s[ty + 1][cx + px + 2], s[ty + 2][cx + px]),
                                 fmaxf(s[ty + 2][cx + px + 1], s[ty + 2][cx + px + 2])));
            if (!(nb > v)) {
                int p = atomicAdd(&c_cnt, 1);
                c_sc[p] = mean;
                c_ix[p] = nOff + gy * W + gx0 + cx + px;
            }
        }
    }
    __syncthreads();
    int cnt = c_cnt;
    if (cnt == 0) return;
    if (tid == 0) c_base = atomicAdd(&g_cand_count[row], cnt);
    __syncthreads();
    int base = c_base;
    for (int i = tid; i < cnt; i += 256) {
        int pos = base + i;
        if (pos < CAP) {
            g_cand_score[row][pos] = c_sc[i];
            g_cand_idx[row][pos]   = c_ix[i];
        }
    }
}

// ---------------- kernel 2: per-row top-512 (bin-bucketed exact rank) ----------------
__global__ void topk_kernel() {
    __shared__ int   hist[1024];
    __shared__ int   sfxs[1025];
    __shared__ int   fill[1024];
    __shared__ int   wtot[32];
    __shared__ int   wtail[32];
    __shared__ float ks_[MKEEP];
    __shared__ int   ki_[MKEEP];
    __shared__ int   s_thr;
    int row = blockIdx.x;
    int tid = threadIdx.x;              // 1024 threads
    int lane = tid & 31, wid = tid >> 5;
    int count = min(g_cand_count[row], CAP);

    hist[tid] = 0;
    fill[tid] = 0;
    if (tid == 0) { s_thr = 0; sfxs[1024] = 0; }
    __syncthreads();

    const float SCL = 1024.0f / 0.3f;
    for (int i = tid; i < count; i += 1024) {
        float sc = g_cand_score[row][i];
        int bb = max(0, min(1023, (int)((sc - THRESH) * SCL)));
        atomicAdd(&hist[bb], 1);
    }
    __syncthreads();

    // suffix count via warp shuffles: sfxs[tid] = sum(hist[tid..1023])
    int h = hist[tid];
    int sfx = h;
    #pragma unroll
    for (int off = 1; off < 32; off <<= 1) {
        int v = __shfl_down_sync(0xffffffffu, sfx, off);
        if (lane < 32 - off) sfx += v;
    }
    int tot = __shfl_sync(0xffffffffu, sfx, 0);   // warp total
    if (lane == 0) wtot[wid] = tot;
    __syncthreads();
    if (tid < 32) {
        int t = wtot[tid];
        int inc = t;
        #pragma unroll
        for (int off = 1; off < 32; off <<= 1) {
            int v = __shfl_down_sync(0xffffffffu, inc, off);
            if (tid < 32 - off) inc += v;
        }
        wtail[tid] = inc - t;     // sum of totals of LATER warps
    }
    __syncthreads();
    {
        int cge = sfx + wtail[wid];
        sfxs[tid] = cge;
        int cge_next = cge - h;
        if (cge >= K_KP && cge_next < K_KP) s_thr = tid;   // unique writer
    }
    __syncthreads();

    int thr = s_thr;
    int kept = min(sfxs[thr], MKEEP);

    // scatter survivors into bin-ordered segments: bin b -> [sfxs[b+1], sfxs[b])
    for (int i = tid; i < count; i += 1024) {
        float sc = g_cand_score[row][i];
        int bb = max(0, min(1023, (int)((sc - THRESH) * SCL)));
        if (bb >= thr) {
            int slot = sfxs[bb + 1] + atomicAdd(&fill[bb], 1);
            if (slot < MKEEP) { ks_[slot] = sc; ki_[slot] = g_cand_idx[row][i]; }
        }
    }
    __syncthreads();

    // exact rank = segment base + within-bin rank (bins strictly ordered by score)
    for (int s2 = tid; s2 < kept; s2 += 1024) {
        float si = ks_[s2]; int ii = ki_[s2];
        int bn = max(0, min(1023, (int)((si - THRESH) * SCL)));
        int lo = sfxs[bn + 1], hi = min(sfxs[bn], kept);
        int rank = lo;
        for (int j = lo; j < hi; ++j) {
            float sj = ks_[j];
            rank += (sj > si) || (sj == si && ki_[j] < ii);
        }
        if (rank < K_KP) { g_kp_score[row][rank] = si; g_kp_idx[row][rank] = ii; }
    }
    __syncthreads();
    if (kept < K_KP) {   // degenerate padding; won't trigger on this data
        for (int r2 = kept + tid; r2 < K_KP; r2 += 1024) {
            g_kp_score[row][r2] = -1.0f;
            g_kp_idx[row][r2]   = r2 - kept;
        }
    }
}

// ---------------- kernel 3: scattered gather (all rows) ----------------
__global__ void gather_kernel(const float* __restrict__ d1s0, const float* __restrict__ d1s1,
                              const float* __restrict__ d2s0, const float* __restrict__ d2s1) {
    int bid = blockIdx.x;
    if (bid == 0 && threadIdx.x < 4) g_cand_count[threadIdx.x] = 0;  // reset for next replay
    int row = bid >> 8;                               // 256 blocks per row
    int t   = (bid & 255) * 256 + threadIdx.x;        // over C*K_KP, kpos fastest
    int ch  = t >> 9;
    int kp  = t & (K_KP - 1);
    int img = row >> 1, b = row & 1;

    int   idx = g_kp_idx[row][kp];
    float sc  = g_kp_score[row][kp];

    const float* dsc; int HW, p;
    if (idx < N0) { dsc = img ? d2s0 : d1s0; HW = N0; p = idx; }
    else          { dsc = img ? d2s1 : d1s1; HW = N1; p = idx - N0; }
    g_desc[row][ch][kp] = __ldg(&dsc[(b * C + ch) * HW + p]) * sc;

    if (ch < 2) {
        int W, pp; float scale;
        if (idx < N0) { W = W0; pp = idx;      scale = 1.0f; }
        else          { W = W1; pp = idx - N0; scale = 2.0f; }
        int r = pp / W, c2 = pp - r * W;
        g_loc[row][ch][kp] = (ch == 0 ? (float)r : (float)c2) * scale;
    }
}

// ---------------- kernel 4: fused qM GEMM + scores + top2/softmax match ----------------
// grid (64, B), 256 threads. Block = 8 q-rows x 512 m.
// Thread tile 4 rows x 4 m: 16 FMA per (LDS.128 bcast + LDS.128) = 2 B/MAC.
// Scores spill to smem, then one warp per row runs the two-pass match.
struct QmS { float qs[C][8]; float Ms[C][C]; };            // 4 KB + 64 KB
union PhU {
    QmS   p1;
    float kss[2][32][K_KP];                                // 131 KB (double buffer)
    float srel[8][K_KP];                                   // 16 KB (reuses dead kss[0])
};

__global__ __launch_bounds__(256)
void relmatch_kernel(const float* __restrict__ Wv) {
    __shared__ __align__(16) float qmsT[C][8];   // [c'][row]
    __shared__ float locs[2][K_KP];
    __shared__ float s_wv[4];
    __shared__ PhU u;
    int b   = blockIdx.y;
    int n0  = blockIdx.x * 8;
    int tid = threadIdx.x;           // 256
    int w   = tid >> 5, lane = tid & 31;
    int krow = 2 + b;

    // ---- prefetch locs (1024 floats = 256 float4) ----
    {
        int ch = tid >> 7, j = (tid & 127) * 4;
        cp16(&locs[ch][j], &g_loc[krow][ch][j]);
    }
    CP_COMMIT();

    // ---- stage q rows + full M ----
    {
        int c = tid >> 1, part = tid & 1;
        float4 v = *(const float4*)&g_desc[b][c][n0 + part * 4];
        *(float4*)&u.p1.qs[c][part * 4] = v;
    }
    #pragma unroll
    for (int k = 0; k < 16; ++k) {           // 4096 float4 of M
        int i = tid + 256 * k;
        int cc = i >> 5, c4 = i & 31;
        cp16(&u.p1.Ms[cc][c4 * 4], &g_M[cc][c4 * 4]);
    }
    CP_COMMIT();
    if (tid < 4) s_wv[tid] = Wv[tid];
    CP_WAIT0();
    __syncthreads();

    // ---- qm[r][c'] = sum_c q[c][r]*M[c][c'];  warp w owns row w ----
    {
        float qacc[4] = {0.f, 0.f, 0.f, 0.f};
        #pragma unroll 4
        for (int cc = 0; cc < C; ++cc) {
            float qc = u.p1.qs[cc][w];
            float4 mv = *(const float4*)&u.p1.Ms[cc][lane * 4];
            qacc[0] += qc * mv.x; qacc[1] += qc * mv.y;
            qacc[2] += qc * mv.z; qacc[3] += qc * mv.w;
        }
        #pragma unroll
        for (int j = 0; j < 4; ++j) qmsT[lane * 4 + j][w] = qacc[j];
    }
    __syncthreads();    // qm done; union region free for kss

    float wv00 = s_wv[0], wv01 = s_wv[1], wv10 = s_wv[2], wv11 = s_wv[3];

    int rg = tid >> 7;               // 0..1 row group (rows rg*4 .. rg*4+3)
    int mq = tid & 127;              // 0..127 m-quad
    int r0 = rg * 4;

    // ---- main GEMM: 4 c-stages, cp.async double buffered ----
    #define STAGE_FILL(buf, c0) do { \
        _Pragma("unroll") \
        for (int k = 0; k < 16; ++k) { \
            int i = tid + 256 * k; \
            int cc = i >> 7, m4 = i & 127; \
            cp16(&u.kss[buf][cc][m4 * 4], &g_desc[krow][(c0) + cc][m4 * 4]); \
        } \
    } while (0)

    STAGE_FILL(0, 0);
    CP_COMMIT();

    float acc[4][4];
    #pragma unroll
    for (int i = 0; i < 4; ++i)
        #pragma unroll
        for (int j = 0; j < 4; ++j) acc[i][j] = 0.f;

    #pragma unroll
    for (int st = 0; st < 4; ++st) {
        if (st < 3) {
            STAGE_FILL((st + 1) & 1, 32 * (st + 1));
            CP_COMMIT();
            CP_WAIT1();
        } else {
            CP_WAIT0();
        }
        __syncthreads();
        int c0 = 32 * st;
        const float* kbase = &u.kss[st & 1][0][mq * 4];
        #pragma unroll
        for (int cc = 0; cc < 32; ++cc) {
            float4 qv = *(const float4*)&qmsT[c0 + cc][r0];   // warp broadcast
            float4 kv = *(const float4*)(kbase + cc * K_KP);
            float qa[4] = {qv.x, qv.y, qv.z, qv.w};
            float ka[4] = {kv.x, kv.y, kv.z, kv.w};
            #pragma unroll
            for (int i = 0; i < 4; ++i)
                #pragma unroll
                for (int j = 0; j < 4; ++j) acc[i][j] += qa[i] * ka[j];
        }
        __syncthreads();
    }
    #undef STAGE_FILL

    // ---- spill scores to smem (srel overlaps dead kss[0] only) ----
    #pragma unroll
    for (int i = 0; i < 4; ++i) {
        float4 v4 = make_float4(acc[i][0], acc[i][1], acc[i][2], acc[i][3]);
        *(float4*)&u.srel[r0 + i][mq * 4] = v4;
    }
    __syncthreads();

    // ---- match: warp w handles row w (two-pass, cached v[16]) ----
    {
        const float* relrow = &u.srel[w][0];
        float v[16];
        #pragma unroll
        for (int t = 0; t < 16; ++t) v[t] = relrow[lane + 32 * t];

        float m1 = -2.0f, m2 = -2.0f;
        #pragma unroll
        for (int t = 0; t < 16; ++t) {
            float x = v[t];
            if (x > m1) { m2 = m1; m1 = x; }
            else if (x > m2) m2 = x;
        }
        #pragma unroll
        for (int off = 16; off; off >>= 1) {
            float o1 = __shfl_down_sync(0xffffffffu, m1, off);
            float o2 = __shfl_down_sync(0xffffffffu, m2, off);
            if (o1 > m1) { m2 = fmaxf(m1, o2); m1 = o1; }
            else         { m2 = fmaxf(m2, o1); }
        }
        m1 = __shfl_sync(0xffffffffu, m1, 0);
        m2 = __shfl_sync(0xffffffffu, m2, 0);

        float sw = 0.0f, y0 = 0.0f, y1 = 0.0f;
        #pragma unroll
        for (int t = 0; t < 16; ++t) {
            int m = lane + 32 * t;
            float wexp = expf(INVTEMP * (v[t] - m1));
            float l0 = locs[0][m], l1 = locs[1][m];
            sw += wexp;
            y0 += wexp * (wv00 * l0 + wv01 * l1);
            y1 += wexp * (wv10 * l0 + wv11 * l1);
        }
        #pragma unroll
        for (int off = 16; off; off >>= 1) {
            sw += __shfl_down_sync(0xffffffffu, sw, off);
            y0 += __shfl_down_sync(0xffffffffu, y0, off);
            y1 += __shfl_down_sync(0xffffffffu, y1, off);
        }
        if (lane == 0) {
            int n = n0 + w;
            float a1 = acosf(fminf(fmaxf(m1, -1.0f), 1.0f));
            float a2 = acosf(fminf(fmaxf(m2, -1.0f), 1.0f));
            g_ratio[b][n] = a1 / a2;
            g_y[b][0][n] = y0 / sw;
            g_y[b][1][n] = y1 / sw;
        }
    }
}

// ---------------- kernel 5: final top-128 by smallest ratio ----------------
__global__ void final_kernel(float* __restrict__ out) {
    __shared__ float rs[K_KP];
    int b = blockIdx.x, tid = threadIdx.x;  // 512
    rs[tid] = g_ratio[b][tid];
    __syncthreads();
    float ri = rs[tid];
    int rank = 0;
    for (int j = 0; j < K_KP; ++j) {
        float rj = rs[j];
        rank += (rj < ri) || (rj == ri && j < tid);
    }
    if (rank < K_MATCH) {
        out[(b * 4 + 0) * K_MATCH + rank] = g_loc[b][0][tid];
        out[(b * 4 + 1) * K_MATCH + rank] = g_loc[b][1][tid];
        out[(b * 4 + 2) * K_MATCH + rank] = g_y[b][0][tid];
        out[(b * 4 + 3) * K_MATCH + rank] = g_y[b][1][tid];
    }
}

// ---------------- launch ----------------
extern "C" void kernel_launch(void* const* d_in, const int* in_sizes, int n_in,
                              void* d_out, int out_size) {
    const float* rep1_s0 = (const float*)d_in[0];
    const float* rel1_s0 = (const float*)d_in[1];
    const float* desc1_s0 = (const float*)d_in[2];
    const float* rep1_s1 = (const float*)d_in[3];
    const float* rel1_s1 = (const float*)d_in[4];
    const float* desc1_s1 = (const float*)d_in[5];
    const float* rep2_s0 = (const float*)d_in[6];
    const float* rel2_s0 = (const float*)d_in[7];
    const float* desc2_s0 = (const float*)d_in[8];
    const float* rep2_s1 = (const float*)d_in[9];
    const float* rel2_s1 = (const float*)d_in[10];
    const float* desc2_s1 = (const float*)d_in[11];
    const float* Wq = (const float*)d_in[12];
    const float* Wk = (const float*)d_in[13];
    const float* Wv = (const float*)d_in[14];
    float* out = (float*)d_out;

    score_all_kernel<<<dim3(W0 / 128, H0 / 8, 9), 256>>>(
        rep1_s0, rel1_s0, rep1_s1, rel1_s1, rep2_s0, rel2_s0, rep2_s1, rel2_s1, Wq, Wk);

    topk_kernel<<<4, 1024>>>();

    gather_kernel<<<1024, 256>>>(desc1_s0, desc1_s1, desc2_s0, desc2_s1);

    relmatch_kernel<<<dim3(K_KP / 8, B), 256>>>(Wv);

    final_kernel<<<B, K_KP>>>(out);
}